// round 1
// baseline (speedup 1.0000x reference)
#include <cuda_runtime.h>
#include <cstdint>

#define D         64
#define EDGE_DIM  16
#define MSG_IN    144
#define UPD_IN    128
#define MAXN      50000

// ---------------- scratch (device globals; no allocation allowed) ----------------
__device__ float g_x[MAXN * D];     // node features between layers
__device__ float g_P[MAXN * D];     // x @ W_i + msg_b   (pairs with dst)
__device__ float g_Q[MAXN * D];     // x @ W_j           (pairs with src)
__device__ float g_agg[MAXN * D];   // scatter-add target
__device__ int   g_is64;            // 1 if edge_index is int64, 0 if int32

typedef unsigned long long u64;

// ---------------- packed f32x2 helpers (Blackwell FFMA2 path) ----------------
__device__ __forceinline__ u64 pack2(float lo, float hi) {
    u64 r; asm("mov.b64 %0, {%1,%2};" : "=l"(r) : "f"(lo), "f"(hi)); return r;
}
__device__ __forceinline__ void fma2(u64& acc, u64 a, u64 b) {
    asm("fma.rn.f32x2 %0, %1, %2, %0;" : "+l"(acc) : "l"(a), "l"(b));
}
__device__ __forceinline__ u64 add2(u64 a, u64 b) {
    u64 r; asm("add.rn.f32x2 %0, %1, %2;" : "=l"(r) : "l"(a), "l"(b)); return r;
}
__device__ __forceinline__ void unpack2(u64 v, float& lo, float& hi) {
    asm("mov.b64 {%0,%1}, %2;" : "=f"(lo), "=f"(hi) : "l"(v));
}

// ---------------- dtype sniffing for edge_index ----------------
// If int64: high 32-bit words are all zero (indices in [0, 50000)).
// If int32: odd words are random indices; P(all 2048 are zero) ~ 0.
__global__ void detect_kernel(const unsigned int* __restrict__ idx) {
    __shared__ unsigned int acc[256];
    unsigned int v = 0;
    for (int i = threadIdx.x; i < 2048; i += 256) v |= idx[2 * i + 1];
    acc[threadIdx.x] = v;
    __syncthreads();
    for (int s = 128; s > 0; s >>= 1) {
        if (threadIdx.x < s) acc[threadIdx.x] |= acc[threadIdx.x + s];
        __syncthreads();
    }
    if (threadIdx.x == 0) g_is64 = (acc[0] == 0u) ? 1 : 0;
}

// ---------------- zero the aggregation buffer ----------------
__global__ void zero_agg_kernel(int n4) {
    int i = blockIdx.x * blockDim.x + threadIdx.x;
    if (i < n4) reinterpret_cast<float4*>(g_agg)[i] = make_float4(0.f, 0.f, 0.f, 0.f);
}

// ---------------- P/Q precompute: P = x @ W[0:64] + b ; Q = x @ W[64:128] ----------------
// blockIdx.y == 0 -> P (with bias), 1 -> Q. One thread per node, 64 accumulators.
__global__ void pq_kernel(const float* __restrict__ xin,
                          const float* __restrict__ msg_w,
                          const float* __restrict__ msg_b,
                          int l, int N) {
    __shared__ __align__(16) float ws[64 * D];
    __shared__ __align__(16) float bs[D];
    const int half = blockIdx.y;
    const float* x_src = xin ? xin : g_x;
    const float* W = msg_w + (size_t)l * MSG_IN * D + (size_t)half * 64 * D;
    for (int i = threadIdx.x; i < 64 * D; i += 256) ws[i] = W[i];
    if (threadIdx.x < D) bs[threadIdx.x] = half ? 0.f : msg_b[l * D + threadIdx.x];
    __syncthreads();

    int v = blockIdx.x * 256 + threadIdx.x;
    if (v >= N) return;

    u64 acc[32];
    const u64* bp = reinterpret_cast<const u64*>(bs);
#pragma unroll
    for (int j = 0; j < 32; j++) acc[j] = bp[j];

    const float4* xr = reinterpret_cast<const float4*>(x_src + (size_t)v * D);
    for (int k4 = 0; k4 < 16; k4++) {
        float4 xv = xr[k4];
#pragma unroll
        for (int c = 0; c < 4; c++) {
            float xs = (c == 0) ? xv.x : (c == 1) ? xv.y : (c == 2) ? xv.z : xv.w;
            u64 a = pack2(xs, xs);
            const ulonglong2* wr = reinterpret_cast<const ulonglong2*>(&ws[(k4 * 4 + c) * D]);
#pragma unroll
            for (int j4 = 0; j4 < 16; j4++) {
                ulonglong2 w = wr[j4];
                fma2(acc[2 * j4],     a, w.x);
                fma2(acc[2 * j4 + 1], a, w.y);
            }
        }
    }
    float* out = (half ? g_Q : g_P) + (size_t)v * D;
    u64* o64 = reinterpret_cast<u64*>(out);
#pragma unroll
    for (int j = 0; j < 32; j++) o64[j] = acc[j];
}

// ---------------- edge pass: agg[dst] += relu(P[dst] + Q[src] + ea @ W_e) ----------------
// 4 threads per edge, each owns 16 output columns. Vectorized red.global.add.v4.f32.
__global__ void edge_kernel(const void* __restrict__ eidx,
                            const float* __restrict__ eattr,
                            const float* __restrict__ msg_w,
                            int l, int E) {
    __shared__ __align__(16) float we[EDGE_DIM * D];   // 4 KB
    const float* W = msg_w + (size_t)l * MSG_IN * D + (size_t)128 * D;
    for (int i = threadIdx.x; i < EDGE_DIM * D; i += 256) we[i] = W[i];
    __syncthreads();

    const int t = threadIdx.x;
    const int e = blockIdx.x * 64 + (t >> 2);
    if (e >= E) return;
    const int c0 = (t & 3) * 16;

    int src, dst;
    if (g_is64) {
        const long long* p = reinterpret_cast<const long long*>(eidx);
        src = (int)p[e];
        dst = (int)p[(size_t)E + e];
    } else {
        const int* p = reinterpret_cast<const int*>(eidx);
        src = p[e];
        dst = p[E + e];
    }

    float eav[16];
    {
        const float4* ep = reinterpret_cast<const float4*>(eattr + (size_t)e * EDGE_DIM);
        *reinterpret_cast<float4*>(&eav[0])  = ep[0];
        *reinterpret_cast<float4*>(&eav[4])  = ep[1];
        *reinterpret_cast<float4*>(&eav[8])  = ep[2];
        *reinterpret_cast<float4*>(&eav[12]) = ep[3];
    }

    u64 r[8];
#pragma unroll
    for (int j = 0; j < 8; j++) r[j] = 0ULL;

#pragma unroll
    for (int k = 0; k < EDGE_DIM; k++) {
        u64 a = pack2(eav[k], eav[k]);
        const ulonglong2* wr = reinterpret_cast<const ulonglong2*>(&we[k * D + c0]);
#pragma unroll
        for (int j4 = 0; j4 < 4; j4++) {
            ulonglong2 w = wr[j4];
            fma2(r[2 * j4],     a, w.x);
            fma2(r[2 * j4 + 1], a, w.y);
        }
    }

    const ulonglong2* Pp = reinterpret_cast<const ulonglong2*>(g_P + (size_t)dst * D + c0);
    const ulonglong2* Qp = reinterpret_cast<const ulonglong2*>(g_Q + (size_t)src * D + c0);
#pragma unroll
    for (int j2 = 0; j2 < 4; j2++) {
        ulonglong2 pv = Pp[j2];
        ulonglong2 qv = Qp[j2];
        r[2 * j2]     = add2(r[2 * j2],     add2(pv.x, qv.x));
        r[2 * j2 + 1] = add2(r[2 * j2 + 1], add2(pv.y, qv.y));
    }

    float* ag = g_agg + (size_t)dst * D + c0;
#pragma unroll
    for (int j2 = 0; j2 < 4; j2++) {
        float a0, a1, a2, a3;
        unpack2(r[2 * j2],     a0, a1);
        unpack2(r[2 * j2 + 1], a2, a3);
        a0 = fmaxf(a0, 0.f); a1 = fmaxf(a1, 0.f);
        a2 = fmaxf(a2, 0.f); a3 = fmaxf(a3, 0.f);
        asm volatile("red.global.add.v4.f32 [%0], {%1,%2,%3,%4};"
                     :: "l"(ag + j2 * 4), "f"(a0), "f"(a1), "f"(a2), "f"(a3)
                     : "memory");
    }
}

// ---------------- node update: x' = relu([x, agg] @ upd_w + b) ----------------
__global__ void upd_kernel(const float* __restrict__ xin,
                           const float* __restrict__ upd_w,
                           const float* __restrict__ upd_b,
                           int l, int N, float* __restrict__ xout) {
    __shared__ __align__(16) float ws[UPD_IN * D];   // 32 KB
    __shared__ __align__(16) float bs[D];
    const float* x_src = xin ? xin : g_x;
    float* x_dst = xout ? xout : g_x;
    const float* W = upd_w + (size_t)l * UPD_IN * D;
    for (int i = threadIdx.x; i < UPD_IN * D; i += 256) ws[i] = W[i];
    if (threadIdx.x < D) bs[threadIdx.x] = upd_b[l * D + threadIdx.x];
    __syncthreads();

    int v = blockIdx.x * 256 + threadIdx.x;
    if (v >= N) return;

    u64 acc[32];
    const u64* bp = reinterpret_cast<const u64*>(bs);
#pragma unroll
    for (int j = 0; j < 32; j++) acc[j] = bp[j];

    const float4* xr = reinterpret_cast<const float4*>(x_src + (size_t)v * D);
    const float4* ar = reinterpret_cast<const float4*>(g_agg + (size_t)v * D);

    for (int k4 = 0; k4 < 16; k4++) {
        float4 xv = xr[k4];
#pragma unroll
        for (int c = 0; c < 4; c++) {
            float xs = (c == 0) ? xv.x : (c == 1) ? xv.y : (c == 2) ? xv.z : xv.w;
            u64 a = pack2(xs, xs);
            const ulonglong2* wr = reinterpret_cast<const ulonglong2*>(&ws[(k4 * 4 + c) * D]);
#pragma unroll
            for (int j4 = 0; j4 < 16; j4++) {
                ulonglong2 w = wr[j4];
                fma2(acc[2 * j4],     a, w.x);
                fma2(acc[2 * j4 + 1], a, w.y);
            }
        }
    }
    for (int k4 = 0; k4 < 16; k4++) {
        float4 av = ar[k4];
#pragma unroll
        for (int c = 0; c < 4; c++) {
            float xs = (c == 0) ? av.x : (c == 1) ? av.y : (c == 2) ? av.z : av.w;
            u64 a = pack2(xs, xs);
            const ulonglong2* wr = reinterpret_cast<const ulonglong2*>(&ws[(64 + k4 * 4 + c) * D]);
#pragma unroll
            for (int j4 = 0; j4 < 16; j4++) {
                ulonglong2 w = wr[j4];
                fma2(acc[2 * j4],     a, w.x);
                fma2(acc[2 * j4 + 1], a, w.y);
            }
        }
    }

    float* o = x_dst + (size_t)v * D;
#pragma unroll
    for (int j = 0; j < 32; j++) {
        float lo, hi;
        unpack2(acc[j], lo, hi);
        float2 rv;
        rv.x = fmaxf(lo, 0.f);
        rv.y = fmaxf(hi, 0.f);
        *reinterpret_cast<float2*>(&o[2 * j]) = rv;
    }
}

// ---------------- launcher ----------------
extern "C" void kernel_launch(void* const* d_in, const int* in_sizes, int n_in,
                              void* d_out, int out_size) {
    const float* x      = (const float*)d_in[0];
    const void*  eidx   = d_in[1];
    const float* eattr  = (const float*)d_in[2];
    const float* msg_w  = (const float*)d_in[3];
    const float* msg_b  = (const float*)d_in[4];
    const float* upd_w  = (const float*)d_in[5];
    const float* upd_b  = (const float*)d_in[6];

    const int N = in_sizes[0] / D;
    const int E = in_sizes[2] / EDGE_DIM;
    const int L = in_sizes[4] / D;

    detect_kernel<<<1, 256>>>((const unsigned int*)eidx);

    const int node_blocks = (N + 255) / 256;
    const int zero_blocks = ((N * D / 4) + 255) / 256;
    const int edge_blocks = (E + 63) / 64;

    for (int l = 0; l < L; l++) {
        const float* xin = (l == 0) ? x : nullptr;           // nullptr -> g_x
        float* xout = (l == L - 1) ? (float*)d_out : nullptr; // nullptr -> g_x

        dim3 pq_grid(node_blocks, 2);
        pq_kernel<<<pq_grid, 256>>>(xin, msg_w, msg_b, l, N);
        zero_agg_kernel<<<zero_blocks, 256>>>(N * D / 4);
        edge_kernel<<<edge_blocks, 256>>>(eidx, eattr, msg_w, l, E);
        upd_kernel<<<node_blocks, 256>>>(xin, upd_w, upd_b, l, N, xout);
    }
}